// round 2
// baseline (speedup 1.0000x reference)
#include <cuda_runtime.h>
#include <cstdint>

#define NN 100000
#define NR 8
#define NE 150000
#define DD 128

// Scratch (device globals: allocation-free per harness rules)
__device__ int   g_deg[NR * NN];                          // 3.2 MB
__device__ __align__(16) float g_msgs[(size_t)NN * DD];   // 51.2 MB, reused per relation

// ---------------------------------------------------------------- index dtype
// Reference declares src/dst int64, but JAX default x64=off silently yields
// int32. Detect on device: int64 data (values < 2^31) has all-zero odd words.
__device__ __forceinline__ bool idx_is64(const int* p) {
    return (p[1] | p[3] | p[5] | p[7]) == 0;
}
__device__ __forceinline__ int idx_at(const void* p, size_t i, bool is64) {
    return is64 ? (int)((const long long*)p)[i] : ((const int*)p)[i];
}

// ---------------------------------------------------------------- zero kernels
__global__ void zero_deg_kernel() {
    int i = blockIdx.x * blockDim.x + threadIdx.x;
    if (i < NR * NN) g_deg[i] = 0;
}

__global__ void zero_msgs_kernel() {
    int i = blockIdx.x * blockDim.x + threadIdx.x;
    float4* p = reinterpret_cast<float4*>(g_msgs);
    if (i < NN * DD / 4) p[i] = make_float4(0.f, 0.f, 0.f, 0.f);
}

// ---------------------------------------------------------------- degree count
__global__ void count_deg_kernel(const void* __restrict__ dst) {
    bool is64 = idx_is64((const int*)dst);
    int e = blockIdx.x * blockDim.x + threadIdx.x;
    int r = blockIdx.y;
    if (e < NE) {
        int d = idx_at(dst, (size_t)r * NE + e, is64);
        atomicAdd(&g_deg[r * NN + d], 1);
    }
}

// ---------------------------------------------------------------- edge scatter
// One warp per edge: gather x[src] (float4/lane), scatter-add into g_msgs[dst].
__global__ void scatter_kernel(const float4* __restrict__ x4,
                               const void* __restrict__ src,
                               const void* __restrict__ dst,
                               int rel) {
    bool is64 = idx_is64((const int*)dst);
    int gw = (blockIdx.x * blockDim.x + threadIdx.x) >> 5;
    int lane = threadIdx.x & 31;
    if (gw >= NE) return;
    int s = idx_at(src, (size_t)rel * NE + gw, is64);
    int d = idx_at(dst, (size_t)rel * NE + gw, is64);
    float4 v = x4[(size_t)s * 32 + lane];
    float* o = g_msgs + (size_t)d * DD + lane * 4;
    atomicAdd(o + 0, v.x);   // return value unused -> REDG
    atomicAdd(o + 1, v.y);
    atomicAdd(o + 2, v.z);
    atomicAdd(o + 3, v.w);
}

// ---------------------------------------------------------------- fp32x2 GEMM
// C[M,128] (+)= (A[M,128] * rowscale) @ W[128,128] (+bias) (relu optional)
// 64 rows x 128 cols per block, 256 threads, packed fma.rn.f32x2 math.
#define TILE_M 64
#define AS_STRIDE 68                       // floats; 272B: 16B-aligned rows
#define SMEM_W_FLOATS (128 * 128)
#define SMEM_BYTES ((SMEM_W_FLOATS + 128 * AS_STRIDE) * 4)

__device__ __forceinline__ unsigned long long dup2(float v) {
    unsigned long long r;
    asm("mov.b64 %0, {%1, %1};" : "=l"(r) : "f"(v));
    return r;
}
__device__ __forceinline__ void fma2(unsigned long long& acc,
                                     unsigned long long a,
                                     unsigned long long b) {
    asm("fma.rn.f32x2 %0, %1, %2, %3;" : "=l"(acc) : "l"(a), "l"(b), "l"(acc));
}
__device__ __forceinline__ float2 unpk(unsigned long long v) {
    float2 f;
    asm("mov.b64 {%0, %1}, %2;" : "=f"(f.x), "=f"(f.y) : "l"(v));
    return f;
}

__global__ __launch_bounds__(256, 2)
void gemm_kernel(const float* __restrict__ Ain,   // null -> g_msgs
                 const float* __restrict__ W,
                 int rel,                          // >=0: scale rows by 1/max(deg,1)
                 const float* __restrict__ bias,   // nullable
                 float* __restrict__ C,
                 int M, int accumulate, int do_relu) {
    extern __shared__ float smem[];
    float* Ws = smem;                       // [128][128]
    float* As = smem + SMEM_W_FLOATS;       // transposed [k][row], stride 68
    const float* A = Ain ? Ain : g_msgs;

    int tid = threadIdx.x;
    int tx = tid & 31;        // col group: cols tx*4..tx*4+3
    int ty = tid >> 5;        // row group: rows ty*8..ty*8+7
    int row0 = blockIdx.x * TILE_M;

    // Load W (64 KB) into SMEM
    const float4* W4 = (const float4*)W;
    float4* Ws4 = (float4*)Ws;
#pragma unroll
    for (int i = 0; i < 16; i++) Ws4[tid + i * 256] = W4[tid + i * 256];

    // Load + transpose A tile (scale by 1/deg folded in here)
#pragma unroll
    for (int i = 0; i < 8; i++) {
        int idx = tid + i * 256;
        int r = idx >> 5;
        int kc = idx & 31;
        int row = row0 + r;
        float4 v = make_float4(0.f, 0.f, 0.f, 0.f);
        if (row < M) {
            v = ((const float4*)A)[(size_t)row * 32 + kc];
            if (rel >= 0) {
                int dg = g_deg[rel * NN + row];
                float sc = 1.0f / (float)(dg > 1 ? dg : 1);
                v.x *= sc; v.y *= sc; v.z *= sc; v.w *= sc;
            }
        }
        int kb = kc * 4;
        As[(kb + 0) * AS_STRIDE + r] = v.x;
        As[(kb + 1) * AS_STRIDE + r] = v.y;
        As[(kb + 2) * AS_STRIDE + r] = v.z;
        As[(kb + 3) * AS_STRIDE + r] = v.w;
    }
    __syncthreads();

    // acc[c][p] packs rows {2p, 2p+1} of column c (relative to this thread)
    unsigned long long acc[4][4];
#pragma unroll
    for (int c = 0; c < 4; c++)
#pragma unroll
        for (int p = 0; p < 4; p++) acc[c][p] = 0ull;

    const float4* Wk = (const float4*)Ws;
#pragma unroll 4
    for (int k = 0; k < 128; k++) {
        float4 w = Wk[k * 32 + tx];
        unsigned long long wd0 = dup2(w.x), wd1 = dup2(w.y),
                           wd2 = dup2(w.z), wd3 = dup2(w.w);
        const ulonglong2* ap = (const ulonglong2*)&As[k * AS_STRIDE + ty * 8];
        ulonglong2 qa = ap[0], qb = ap[1];       // 8 row-values as 4 packed pairs
        unsigned long long a2[4] = {qa.x, qa.y, qb.x, qb.y};
#pragma unroll
        for (int p = 0; p < 4; p++) {
            fma2(acc[0][p], a2[p], wd0);
            fma2(acc[1][p], a2[p], wd1);
            fma2(acc[2][p], a2[p], wd2);
            fma2(acc[3][p], a2[p], wd3);
        }
    }

    // Epilogue
    float4 bv = make_float4(0.f, 0.f, 0.f, 0.f);
    if (bias) bv = ((const float4*)bias)[tx];
#pragma unroll
    for (int p = 0; p < 4; p++) {
        float2 c0 = unpk(acc[0][p]);
        float2 c1 = unpk(acc[1][p]);
        float2 c2 = unpk(acc[2][p]);
        float2 c3 = unpk(acc[3][p]);
        int row = row0 + ty * 8 + p * 2;
#pragma unroll
        for (int h = 0; h < 2; h++) {
            int rr = row + h;
            if (rr >= M) continue;
            float4 v = (h == 0) ? make_float4(c0.x, c1.x, c2.x, c3.x)
                                : make_float4(c0.y, c1.y, c2.y, c3.y);
            v.x += bv.x; v.y += bv.y; v.z += bv.z; v.w += bv.w;
            float4* Cp = (float4*)C + (size_t)rr * 32 + tx;
            if (accumulate) {
                float4 o = *Cp;
                v.x += o.x; v.y += o.y; v.z += o.z; v.w += o.w;
            }
            if (do_relu) {
                v.x = fmaxf(v.x, 0.f); v.y = fmaxf(v.y, 0.f);
                v.z = fmaxf(v.z, 0.f); v.w = fmaxf(v.w, 0.f);
            }
            *Cp = v;
        }
    }
}

// ---------------------------------------------------------------- launch
extern "C" void kernel_launch(void* const* d_in, const int* in_sizes, int n_in,
                              void* d_out, int out_size) {
    const float* x    = (const float*)d_in[0];
    const float* w    = (const float*)d_in[1];   // [8][128][128]
    const float* wsl  = (const float*)d_in[2];   // [128][128]
    const float* bias = (const float*)d_in[3];   // [128]
    const void* src   = d_in[4];                 // [8][150000] int32 or int64
    const void* dst   = d_in[5];                 // [8][150000] int32 or int64
    float* out = (float*)d_out;                  // [100000][128]

    cudaFuncSetAttribute(gemm_kernel,
                         cudaFuncAttributeMaxDynamicSharedMemorySize,
                         SMEM_BYTES);

    // 1) degrees for all relations
    zero_deg_kernel<<<(NR * NN + 255) / 256, 256>>>();
    dim3 cg((NE + 255) / 256, NR);
    count_deg_kernel<<<cg, 256>>>(dst);

    // 2) self-loop GEMM initializes out (beta=0, +bias)
    int gblocks = (NN + TILE_M - 1) / TILE_M;
    gemm_kernel<<<gblocks, 256, SMEM_BYTES>>>(x, wsl, -1, bias, out, NN, 0, 0);

    // 3) per relation: zero msgs -> scatter-sum -> GEMM-accumulate
    //    (1/deg folded into GEMM A-load, relu folded into last GEMM)
    for (int r = 0; r < NR; r++) {
        zero_msgs_kernel<<<(NN * DD / 4 + 255) / 256, 256>>>();
        scatter_kernel<<<(NE * 32 + 255) / 256, 256>>>(
            (const float4*)x, src, dst, r);
        gemm_kernel<<<gblocks, 256, SMEM_BYTES>>>(
            nullptr, w + (size_t)r * DD * DD, r, nullptr, out, NN, 1,
            (r == NR - 1) ? 1 : 0);
    }
}

// round 7
// speedup vs baseline: 1.0559x; 1.0559x over previous
#include <cuda_runtime.h>
#include <cuda_bf16.h>
#include <cstdint>

#define NN 100000
#define NR 8
#define NE 150000
#define DD 128
#define MT 128
#define NTILES ((NN + MT - 1) / MT)

// Scratch (device globals: allocation-free per harness rules)
__device__ int   g_deg[NR * NN];                          // 3.2 MB
__device__ __align__(16) float g_msgs[(size_t)NN * DD];   // 51.2 MB
// W in mma-fragment order: [rel(9)][kk(8)][pair(8)][lane(32)] x uint4
__device__ __align__(16) uint4 g_wf_hi[9 * 8 * 8 * 32];   // 288 KB
__device__ __align__(16) uint4 g_wf_lo[9 * 8 * 8 * 32];   // 288 KB

// ---------------------------------------------------------------- index dtype
__device__ __forceinline__ bool idx_is64(const int* p) {
    return (p[1] | p[3] | p[5] | p[7]) == 0;
}
__device__ __forceinline__ int idx_at(const void* p, size_t i, bool is64) {
    return is64 ? (int)((const long long*)p)[i] : ((const int*)p)[i];
}

// ---------------------------------------------------------------- small kernels
__global__ void zero_deg_kernel() {
    int i = blockIdx.x * blockDim.x + threadIdx.x;
    if (i < NR * NN) g_deg[i] = 0;
}
__global__ void zero_msgs_kernel() {
    int i = blockIdx.x * blockDim.x + threadIdx.x;
    float4* p = reinterpret_cast<float4*>(g_msgs);
    if (i < NN * DD / 4) p[i] = make_float4(0.f, 0.f, 0.f, 0.f);
}
__global__ void count_deg_kernel(const void* __restrict__ dst) {
    bool is64 = idx_is64((const int*)dst);
    int e = blockIdx.x * blockDim.x + threadIdx.x;
    int r = blockIdx.y;
    if (e < NE) {
        int d = idx_at(dst, (size_t)r * NE + e, is64);
        atomicAdd(&g_deg[r * NN + d], 1);
    }
}

__device__ __forceinline__ uint32_t pack_bf2(float a, float b) {
    __nv_bfloat162 h = __floats2bfloat162_rn(a, b);
    return *(uint32_t*)&h;
}

// W prep into fragment order. rel 8 = self-loop weight.
// For lane: g=lane>>2, tk=lane&3. uint4 = {b0(nA), b1(nA), b0(nB), b1(nB)}
// b0 = {W[k0][n], W[k0+1][n]}, b1 = {W[k0+8][n], W[k0+9][n]}, k0=kk*16+tk*2,
// nA = pair*16+g, nB = nA+8.
__global__ void prep_w_kernel(const float* __restrict__ w,
                              const float* __restrict__ wsl) {
    int i = blockIdx.x * blockDim.x + threadIdx.x;
    if (i >= 9 * 8 * 8 * 32) return;
    int lane = i & 31, p = (i >> 5) & 7, kk = (i >> 8) & 7, rel = i >> 11;
    int g = lane >> 2, tk = lane & 3;
    const float* B = (rel < 8) ? w + (size_t)rel * DD * DD : wsl;
    int k0 = kk * 16 + tk * 2;
    int nA = p * 16 + g, nB = nA + 8;
    float v[8];
    v[0] = B[(k0 + 0) * DD + nA]; v[1] = B[(k0 + 1) * DD + nA];
    v[2] = B[(k0 + 8) * DD + nA]; v[3] = B[(k0 + 9) * DD + nA];
    v[4] = B[(k0 + 0) * DD + nB]; v[5] = B[(k0 + 1) * DD + nB];
    v[6] = B[(k0 + 8) * DD + nB]; v[7] = B[(k0 + 9) * DD + nB];
    uint32_t hq[4], lq[4];
#pragma unroll
    for (int q = 0; q < 4; q++) {
        float a = v[2 * q], b = v[2 * q + 1];
        __nv_bfloat16 ha = __float2bfloat16(a), hb = __float2bfloat16(b);
        hq[q] = pack_bf2(a, b);  // RN-pack of (a,b)
        lq[q] = pack_bf2(a - __bfloat162float(ha), b - __bfloat162float(hb));
    }
    g_wf_hi[i] = make_uint4(hq[0], hq[1], hq[2], hq[3]);
    g_wf_lo[i] = make_uint4(lq[0], lq[1], lq[2], lq[3]);
}

// ---------------------------------------------------------------- edge scatter
__global__ void scatter_kernel(const float4* __restrict__ x4,
                               const void* __restrict__ src,
                               const void* __restrict__ dst,
                               int rel) {
    bool is64 = idx_is64((const int*)dst);
    int gw = (blockIdx.x * blockDim.x + threadIdx.x) >> 5;
    int lane = threadIdx.x & 31;
    if (gw >= NE) return;
    int s = idx_at(src, (size_t)rel * NE + gw, is64);
    int d = idx_at(dst, (size_t)rel * NE + gw, is64);
    float4 v = x4[(size_t)s * 32 + lane];
    float* o = g_msgs + (size_t)d * DD + lane * 4;
    atomicAdd(o + 0, v.x);
    atomicAdd(o + 1, v.y);
    atomicAdd(o + 2, v.z);
    atomicAdd(o + 3, v.w);
}

// ---------------------------------------------------------------- mma helpers
__device__ __forceinline__ uint32_t smem_u32(const void* p) {
    uint32_t a;
    asm("{ .reg .u64 t; cvta.to.shared.u64 t, %1; cvt.u32.u64 %0, t; }"
        : "=r"(a) : "l"(p));
    return a;
}
__device__ __forceinline__ void ldsm4(uint32_t* a, uint32_t addr) {
    asm volatile("ldmatrix.sync.aligned.m8n8.x4.shared.b16 {%0,%1,%2,%3}, [%4];"
                 : "=r"(a[0]), "=r"(a[1]), "=r"(a[2]), "=r"(a[3]) : "r"(addr));
}
__device__ __forceinline__ void mma16816(float* c, const uint32_t* a,
                                         uint32_t b0, uint32_t b1) {
    asm volatile(
        "mma.sync.aligned.m16n8k16.row.col.f32.bf16.bf16.f32 "
        "{%0,%1,%2,%3}, {%4,%5,%6,%7}, {%8,%9}, {%0,%1,%2,%3};"
        : "+f"(c[0]), "+f"(c[1]), "+f"(c[2]), "+f"(c[3])
        : "r"(a[0]), "r"(a[1]), "r"(a[2]), "r"(a[3]), "r"(b0), "r"(b1));
}

// ---------------------------------------------------------------- HMMA GEMM
// C[128-tile,128] (+)= split_bf16(A*rowscale) @ split_bf16(W) (+bias, relu)
// A hi/lo in SMEM (row stride 272B), W from g_wf via LDG.128 fragments.
#define ARS 272                       // A smem row stride, bytes
#define A_PLANE (128 * ARS)           // 34816 B per plane
#define GEMM_SMEM (2 * A_PLANE)       // 69632 B

__global__ __launch_bounds__(256)
void gemm_mma_kernel(const float* __restrict__ Ain,   // null -> g_msgs
                     int rel,                          // >=0: rows /= max(deg,1)
                     int wsel,                         // 0..8 into g_wf
                     const float* __restrict__ bias,   // nullable
                     float* __restrict__ C,
                     int accumulate, int do_relu, int clear_msgs) {
    extern __shared__ char sm[];
    const float* A = Ain ? Ain : g_msgs;
    int tid = threadIdx.x, lane = tid & 31, w = tid >> 5;
    int wm = w & 1, wn = w >> 1;
    int row0 = blockIdx.x * MT;

    // ---- convert A tile: 2 threads per row (halves), fp32 -> hi/lo bf16
    {
        int row = tid >> 1;
        int grow = row0 + row;
        char* hiB = sm + row * ARS + (tid & 1) * 128;
        char* loB = hiB + A_PLANE;
        if (grow < NN) {
            float sc = 1.f;
            if (rel >= 0) {
                int dg = g_deg[rel * NN + grow];
                sc = 1.f / (float)(dg > 1 ? dg : 1);
            }
            const float4* Ar = (const float4*)A + (size_t)grow * 32 + (tid & 1) * 16;
#pragma unroll 4
            for (int j = 0; j < 16; j++) {
                float4 v = Ar[j];
                v.x *= sc; v.y *= sc; v.z *= sc; v.w *= sc;
                __nv_bfloat162 h01 = __floats2bfloat162_rn(v.x, v.y);
                __nv_bfloat162 h23 = __floats2bfloat162_rn(v.z, v.w);
                uint2 hu = make_uint2(*(uint32_t*)&h01, *(uint32_t*)&h23);
                uint2 lu = make_uint2(
                    pack_bf2(v.x - __bfloat162float(h01.x),
                             v.y - __bfloat162float(h01.y)),
                    pack_bf2(v.z - __bfloat162float(h23.x),
                             v.w - __bfloat162float(h23.y)));
                *(uint2*)(hiB + j * 8) = hu;
                *(uint2*)(loB + j * 8) = lu;
            }
            if (clear_msgs) {   // pre-zero this tile for the next relation
                float4 z = make_float4(0.f, 0.f, 0.f, 0.f);
                float4* Mz = (float4*)g_msgs + (size_t)grow * 32 + (tid & 1) * 16;
#pragma unroll 4
                for (int j = 0; j < 16; j++) Mz[j] = z;
            }
        } else {
            uint2 z = make_uint2(0u, 0u);
#pragma unroll 4
            for (int j = 0; j < 16; j++) {
                *(uint2*)(hiB + j * 8) = z;
                *(uint2*)(loB + j * 8) = z;
            }
        }
    }
    __syncthreads();

    // ---- mainloop
    float acc[4][4][4];
#pragma unroll
    for (int i = 0; i < 4; i++)
#pragma unroll
        for (int j = 0; j < 4; j++)
#pragma unroll
            for (int q = 0; q < 4; q++) acc[i][j][q] = 0.f;

    uint32_t sb = smem_u32(sm);
    // ldmatrix per-lane base: row = wm*64 + (lane&15), col-half = (lane>>4)*8
    uint32_t aBase = sb + (wm * 64 + (lane & 15)) * ARS + (lane >> 4) * 16;
    const uint4* WH = g_wf_hi + ((size_t)wsel * 8 * 8 + wn * 2) * 32 + lane;
    const uint4* WL = g_wf_lo + ((size_t)wsel * 8 * 8 + wn * 2) * 32 + lane;

    // Phase 1: A_hi x (W_hi, W_lo)
#pragma unroll
    for (int kk = 0; kk < 8; kk++) {
        uint32_t a[4][4];
#pragma unroll
        for (int i = 0; i < 4; i++)
            ldsm4(a[i], aBase + i * 16 * ARS + kk * 32);
        uint4 f0 = WH[kk * 8 * 32], f1 = WH[kk * 8 * 32 + 32];
#pragma unroll
        for (int i = 0; i < 4; i++) {
            mma16816(acc[i][0], a[i], f0.x, f0.y);
            mma16816(acc[i][1], a[i], f0.z, f0.w);
            mma16816(acc[i][2], a[i], f1.x, f1.y);
            mma16816(acc[i][3], a[i], f1.z, f1.w);
        }
        uint4 g0 = WL[kk * 8 * 32], g1 = WL[kk * 8 * 32 + 32];
#pragma unroll
        for (int i = 0; i < 4; i++) {
            mma16816(acc[i][0], a[i], g0.x, g0.y);
            mma16816(acc[i][1], a[i], g0.z, g0.w);
            mma16816(acc[i][2], a[i], g1.x, g1.y);
            mma16816(acc[i][3], a[i], g1.z, g1.w);
        }
    }
    // Phase 2: A_lo x W_hi
#pragma unroll
    for (int kk = 0; kk < 8; kk++) {
        uint32_t a[4][4];
#pragma unroll
        for (int i = 0; i < 4; i++)
            ldsm4(a[i], aBase + A_PLANE + i * 16 * ARS + kk * 32);
        uint4 f0 = WH[kk * 8 * 32], f1 = WH[kk * 8 * 32 + 32];
#pragma unroll
        for (int i = 0; i < 4; i++) {
            mma16816(acc[i][0], a[i], f0.x, f0.y);
            mma16816(acc[i][1], a[i], f0.z, f0.w);
            mma16816(acc[i][2], a[i], f1.x, f1.y);
            mma16816(acc[i][3], a[i], f1.z, f1.w);
        }
    }

    // ---- epilogue
    int g = lane >> 2, tk = lane & 3;
#pragma unroll
    for (int i = 0; i < 4; i++) {
        int r1 = row0 + wm * 64 + i * 16 + g;
#pragma unroll
        for (int jl = 0; jl < 4; jl++) {
            int c = wn * 32 + jl * 8 + tk * 2;
            float b0 = 0.f, b1 = 0.f;
            if (bias) { b0 = bias[c]; b1 = bias[c + 1]; }
#pragma unroll
            for (int h = 0; h < 2; h++) {
                int row = r1 + h * 8;
                if (row < NN) {
                    float2* p = (float2*)(C + (size_t)row * DD + c);
                    float2 v = make_float2(acc[i][jl][h * 2] + b0,
                                           acc[i][jl][h * 2 + 1] + b1);
                    if (accumulate) {
                        float2 o = *p;
                        v.x += o.x; v.y += o.y;
                    }
                    if (do_relu) { v.x = fmaxf(v.x, 0.f); v.y = fmaxf(v.y, 0.f); }
                    *p = v;
                }
            }
        }
    }
}

// ---------------------------------------------------------------- launch
extern "C" void kernel_launch(void* const* d_in, const int* in_sizes, int n_in,
                              void* d_out, int out_size) {
    const float* x    = (const float*)d_in[0];
    const float* w    = (const float*)d_in[1];
    const float* wsl  = (const float*)d_in[2];
    const float* bias = (const float*)d_in[3];
    const void* src   = d_in[4];
    const void* dst   = d_in[5];
    float* out = (float*)d_out;

    cudaFuncSetAttribute(gemm_mma_kernel,
                         cudaFuncAttributeMaxDynamicSharedMemorySize, GEMM_SMEM);

    // 1) degrees + W fragment prep + one-time msgs zero
    zero_deg_kernel<<<(NR * NN + 255) / 256, 256>>>();
    dim3 cg((NE + 255) / 256, NR);
    count_deg_kernel<<<cg, 256>>>(dst);
    prep_w_kernel<<<(9 * 8 * 8 * 32 + 255) / 256, 256>>>(w, wsl);
    zero_msgs_kernel<<<(NN * DD / 4 + 255) / 256, 256>>>();

    // 2) self-loop GEMM initializes out (beta=0, +bias)
    gemm_mma_kernel<<<NTILES, 256, GEMM_SMEM>>>(x, -1, 8, bias, out, 0, 0, 0);

    // 3) per relation: scatter-sum -> GEMM-accumulate (GEMM re-zeroes msgs
    //    tile for the next relation; relu folded into last GEMM)
    for (int r = 0; r < NR; r++) {
        scatter_kernel<<<(NE * 32 + 255) / 256, 256>>>(
            (const float4*)x, src, dst, r);
        gemm_mma_kernel<<<NTILES, 256, GEMM_SMEM>>>(
            nullptr, r, r, nullptr, out, 1, (r == NR - 1) ? 1 : 0,
            (r < NR - 1) ? 1 : 0);
    }
}

// round 8
// speedup vs baseline: 2.1774x; 2.0620x over previous
#include <cuda_runtime.h>
#include <cuda_bf16.h>
#include <cstdint>

#define NN 100000
#define NR 8
#define NE 150000
#define DD 128
#define MT 128
#define NTILES ((NN + MT - 1) / MT)

// Scratch (device globals: allocation-free per harness rules)
__device__ int g_deg[NR * NN];       // in-degree per relation
__device__ int g_fill[NR * NN];      // bucket-fill cursors
__device__ int g_rowptr[NR * NN];    // CSR exclusive offsets
__device__ int g_esrc[NR * NE];      // CSR src lists
// W in mma-fragment order: [rel(9)][kk(8)][pair(8)][lane(32)] x uint4
__device__ __align__(16) uint4 g_wf_hi[9 * 8 * 8 * 32];   // 288 KB
__device__ __align__(16) uint4 g_wf_lo[9 * 8 * 8 * 32];   // 288 KB

// ---------------------------------------------------------------- index dtype
__device__ __forceinline__ bool idx_is64(const int* p) {
    return (p[1] | p[3] | p[5] | p[7]) == 0;
}
__device__ __forceinline__ int idx_at(const void* p, size_t i, bool is64) {
    return is64 ? (int)((const long long*)p)[i] : ((const int*)p)[i];
}

// ---------------------------------------------------------------- setup kernels
__global__ void zero_kernel() {
    int i = blockIdx.x * blockDim.x + threadIdx.x;
    if (i < NR * NN) { g_deg[i] = 0; g_fill[i] = 0; }
}
__global__ void count_deg_kernel(const void* __restrict__ dst) {
    bool is64 = idx_is64((const int*)dst);
    int e = blockIdx.x * blockDim.x + threadIdx.x;
    int r = blockIdx.y;
    if (e < NE) {
        int d = idx_at(dst, (size_t)r * NE + e, is64);
        atomicAdd(&g_deg[r * NN + d], 1);
    }
}

// Exclusive prefix sum of g_deg -> g_rowptr, one block per relation.
__global__ void scan_kernel() {
    int r = blockIdx.x;
    int t = threadIdx.x;                       // 1024 threads
    int lane = t & 31, wid = t >> 5;
    __shared__ int wsum[32];
    __shared__ int carry_s;
    if (t == 0) carry_s = 0;
    __syncthreads();
    for (int base = 0; base < NN; base += 1024) {
        int i = base + t;
        int v = (i < NN) ? g_deg[r * NN + i] : 0;
        // warp inclusive scan
        int s = v;
#pragma unroll
        for (int off = 1; off < 32; off <<= 1) {
            int n = __shfl_up_sync(0xFFFFFFFFu, s, off);
            if (lane >= off) s += n;
        }
        if (lane == 31) wsum[wid] = s;
        __syncthreads();
        if (wid == 0) {
            int ws = wsum[lane];
#pragma unroll
            for (int off = 1; off < 32; off <<= 1) {
                int n = __shfl_up_sync(0xFFFFFFFFu, ws, off);
                if (lane >= off) ws += n;
            }
            wsum[lane] = ws;
        }
        __syncthreads();
        int incl = s + (wid > 0 ? wsum[wid - 1] : 0);
        int carry = carry_s;
        if (i < NN) g_rowptr[r * NN + i] = carry + incl - v;
        __syncthreads();
        if (t == 1023) carry_s = carry + incl;
        __syncthreads();
    }
}

__global__ void fill_kernel(const void* __restrict__ src,
                            const void* __restrict__ dst) {
    bool is64 = idx_is64((const int*)dst);
    int e = blockIdx.x * blockDim.x + threadIdx.x;
    int r = blockIdx.y;
    if (e < NE) {
        int s = idx_at(src, (size_t)r * NE + e, is64);
        int d = idx_at(dst, (size_t)r * NE + e, is64);
        int pos = atomicAdd(&g_fill[r * NN + d], 1);
        g_esrc[(size_t)r * NE + g_rowptr[r * NN + d] + pos] = s;
    }
}

__device__ __forceinline__ uint32_t pack_bf2(float a, float b) {
    __nv_bfloat162 h = __floats2bfloat162_rn(a, b);
    return *(uint32_t*)&h;
}

// W prep into fragment order. rel 8 = self-loop weight. (proven in round 7)
__global__ void prep_w_kernel(const float* __restrict__ w,
                              const float* __restrict__ wsl) {
    int i = blockIdx.x * blockDim.x + threadIdx.x;
    if (i >= 9 * 8 * 8 * 32) return;
    int lane = i & 31, p = (i >> 5) & 7, kk = (i >> 8) & 7, rel = i >> 11;
    int g = lane >> 2, tk = lane & 3;
    const float* B = (rel < 8) ? w + (size_t)rel * DD * DD : wsl;
    int k0 = kk * 16 + tk * 2;
    int nA = p * 16 + g, nB = nA + 8;
    float v[8];
    v[0] = B[(k0 + 0) * DD + nA]; v[1] = B[(k0 + 1) * DD + nA];
    v[2] = B[(k0 + 8) * DD + nA]; v[3] = B[(k0 + 9) * DD + nA];
    v[4] = B[(k0 + 0) * DD + nB]; v[5] = B[(k0 + 1) * DD + nB];
    v[6] = B[(k0 + 8) * DD + nB]; v[7] = B[(k0 + 9) * DD + nB];
    uint32_t hq[4], lq[4];
#pragma unroll
    for (int q = 0; q < 4; q++) {
        float a = v[2 * q], b = v[2 * q + 1];
        __nv_bfloat16 ha = __float2bfloat16(a), hb = __float2bfloat16(b);
        hq[q] = pack_bf2(a, b);
        lq[q] = pack_bf2(a - __bfloat162float(ha), b - __bfloat162float(hb));
    }
    g_wf_hi[i] = make_uint4(hq[0], hq[1], hq[2], hq[3]);
    g_wf_lo[i] = make_uint4(lq[0], lq[1], lq[2], lq[3]);
}

// ---------------------------------------------------------------- mma helpers
__device__ __forceinline__ uint32_t smem_u32(const void* p) {
    uint32_t a;
    asm("{ .reg .u64 t; cvta.to.shared.u64 t, %1; cvt.u32.u64 %0, t; }"
        : "=r"(a) : "l"(p));
    return a;
}
__device__ __forceinline__ void ldsm4(uint32_t* a, uint32_t addr) {
    asm volatile("ldmatrix.sync.aligned.m8n8.x4.shared.b16 {%0,%1,%2,%3}, [%4];"
                 : "=r"(a[0]), "=r"(a[1]), "=r"(a[2]), "=r"(a[3]) : "r"(addr));
}
__device__ __forceinline__ void mma16816(float* c, const uint32_t* a,
                                         uint32_t b0, uint32_t b1) {
    asm volatile(
        "mma.sync.aligned.m16n8k16.row.col.f32.bf16.bf16.f32 "
        "{%0,%1,%2,%3}, {%4,%5,%6,%7}, {%8,%9}, {%0,%1,%2,%3};"
        : "+f"(c[0]), "+f"(c[1]), "+f"(c[2]), "+f"(c[3])
        : "r"(a[0]), "r"(a[1]), "r"(a[2]), "r"(a[3]), "r"(b0), "r"(b1));
}

// ---------------------------------------------------------------- fused kernel
// One 128-row tile per block. Loops self-loop + 8 relations; each pass
// gathers/normalizes A from CSR (or copies x), splits to bf16 hi/lo in SMEM,
// and accumulates split-MMA into persistent registers. Single bias+relu store.
#define ARS 272                       // A smem row stride, bytes
#define A_PLANE (128 * ARS)           // 34816 B per plane
#define GEMM_SMEM (2 * A_PLANE)       // 69632 B

__global__ __launch_bounds__(256, 1)
void fused_gemm_kernel(const float* __restrict__ x,
                       const float* __restrict__ bias,
                       float* __restrict__ C) {
    extern __shared__ char sm[];
    int tid = threadIdx.x, lane = tid & 31, w = tid >> 5;
    int wm = w & 1, wn = w >> 1;
    int row0 = blockIdx.x * MT;

    float acc[4][4][4];
#pragma unroll
    for (int i = 0; i < 4; i++)
#pragma unroll
        for (int j = 0; j < 4; j++)
#pragma unroll
            for (int q = 0; q < 4; q++) acc[i][j][q] = 0.f;

    uint32_t sb = smem_u32(sm);
    uint32_t aBase = sb + (wm * 64 + (lane & 15)) * ARS + (lane >> 4) * 16;

    for (int rs = 0; rs < 9; rs++) {
        int rel = rs - 1;                       // rs=0 -> self-loop (A = x)
        int wsel = (rel < 0) ? 8 : rel;

        // ---- A phase: 4 threads per row (quarter-rows), 2 passes
#pragma unroll
        for (int pass = 0; pass < 2; pass++) {
            int row = pass * 64 + (tid >> 2);
            int quad = tid & 3;                  // 32-float chunk
            int grow = row0 + row;
            char* hiB = sm + row * ARS + quad * 64;
            char* loB = hiB + A_PLANE;
            float4 a4[8];
#pragma unroll
            for (int j = 0; j < 8; j++) a4[j] = make_float4(0.f, 0.f, 0.f, 0.f);
            if (grow < NN) {
                if (rel < 0) {
                    const float4* Ar = (const float4*)x + (size_t)grow * 32 + quad * 8;
#pragma unroll
                    for (int j = 0; j < 8; j++) a4[j] = Ar[j];
                } else {
                    int dg = g_deg[rel * NN + grow];
                    int rp = g_rowptr[rel * NN + grow];
                    const int* ep = g_esrc + (size_t)rel * NE + rp;
                    for (int e = 0; e < dg; e++) {
                        int s = ep[e];
                        const float4* Xr = (const float4*)x + (size_t)s * 32 + quad * 8;
#pragma unroll
                        for (int j = 0; j < 8; j++) {
                            float4 v = Xr[j];
                            a4[j].x += v.x; a4[j].y += v.y;
                            a4[j].z += v.z; a4[j].w += v.w;
                        }
                    }
                    float sc = 1.f / (float)(dg > 1 ? dg : 1);
#pragma unroll
                    for (int j = 0; j < 8; j++) {
                        a4[j].x *= sc; a4[j].y *= sc;
                        a4[j].z *= sc; a4[j].w *= sc;
                    }
                }
            }
#pragma unroll
            for (int j = 0; j < 8; j++) {
                float4 v = a4[j];
                __nv_bfloat162 h01 = __floats2bfloat162_rn(v.x, v.y);
                __nv_bfloat162 h23 = __floats2bfloat162_rn(v.z, v.w);
                *(uint2*)(hiB + j * 8) =
                    make_uint2(*(uint32_t*)&h01, *(uint32_t*)&h23);
                *(uint2*)(loB + j * 8) = make_uint2(
                    pack_bf2(v.x - __bfloat162float(h01.x),
                             v.y - __bfloat162float(h01.y)),
                    pack_bf2(v.z - __bfloat162float(h23.x),
                             v.w - __bfloat162float(h23.y)));
            }
        }
        __syncthreads();

        // ---- MMA phase (accumulates into persistent acc)
        const uint4* WH = g_wf_hi + ((size_t)wsel * 8 * 8 + wn * 2) * 32 + lane;
        const uint4* WL = g_wf_lo + ((size_t)wsel * 8 * 8 + wn * 2) * 32 + lane;
        // Phase 1: A_hi x (W_hi + W_lo)
#pragma unroll
        for (int kk = 0; kk < 8; kk++) {
            uint32_t a[4][4];
#pragma unroll
            for (int i = 0; i < 4; i++)
                ldsm4(a[i], aBase + i * 16 * ARS + kk * 32);
            uint4 f0 = WH[kk * 8 * 32], f1 = WH[kk * 8 * 32 + 32];
#pragma unroll
            for (int i = 0; i < 4; i++) {
                mma16816(acc[i][0], a[i], f0.x, f0.y);
                mma16816(acc[i][1], a[i], f0.z, f0.w);
                mma16816(acc[i][2], a[i], f1.x, f1.y);
                mma16816(acc[i][3], a[i], f1.z, f1.w);
            }
            uint4 g0 = WL[kk * 8 * 32], g1 = WL[kk * 8 * 32 + 32];
#pragma unroll
            for (int i = 0; i < 4; i++) {
                mma16816(acc[i][0], a[i], g0.x, g0.y);
                mma16816(acc[i][1], a[i], g0.z, g0.w);
                mma16816(acc[i][2], a[i], g1.x, g1.y);
                mma16816(acc[i][3], a[i], g1.z, g1.w);
            }
        }
        // Phase 2: A_lo x W_hi
#pragma unroll
        for (int kk = 0; kk < 8; kk++) {
            uint32_t a[4][4];
#pragma unroll
            for (int i = 0; i < 4; i++)
                ldsm4(a[i], aBase + A_PLANE + i * 16 * ARS + kk * 32);
            uint4 f0 = WH[kk * 8 * 32], f1 = WH[kk * 8 * 32 + 32];
#pragma unroll
            for (int i = 0; i < 4; i++) {
                mma16816(acc[i][0], a[i], f0.x, f0.y);
                mma16816(acc[i][1], a[i], f0.z, f0.w);
                mma16816(acc[i][2], a[i], f1.x, f1.y);
                mma16816(acc[i][3], a[i], f1.z, f1.w);
            }
        }
        __syncthreads();   // protect SMEM reuse by next relation
    }

    // ---- single epilogue: + bias, relu, store
    int g = lane >> 2, tk = lane & 3;
#pragma unroll
    for (int i = 0; i < 4; i++) {
        int r1 = row0 + wm * 64 + i * 16 + g;
#pragma unroll
        for (int jl = 0; jl < 4; jl++) {
            int c = wn * 32 + jl * 8 + tk * 2;
            float b0 = bias[c], b1 = bias[c + 1];
#pragma unroll
            for (int h = 0; h < 2; h++) {
                int row = r1 + h * 8;
                if (row < NN) {
                    float2 v = make_float2(
                        fmaxf(acc[i][jl][h * 2] + b0, 0.f),
                        fmaxf(acc[i][jl][h * 2 + 1] + b1, 0.f));
                    *(float2*)(C + (size_t)row * DD + c) = v;
                }
            }
        }
    }
}

// ---------------------------------------------------------------- launch
extern "C" void kernel_launch(void* const* d_in, const int* in_sizes, int n_in,
                              void* d_out, int out_size) {
    const float* x    = (const float*)d_in[0];
    const float* w    = (const float*)d_in[1];
    const float* wsl  = (const float*)d_in[2];
    const float* bias = (const float*)d_in[3];
    const void* src   = d_in[4];
    const void* dst   = d_in[5];
    float* out = (float*)d_out;

    cudaFuncSetAttribute(fused_gemm_kernel,
                         cudaFuncAttributeMaxDynamicSharedMemorySize, GEMM_SMEM);

    // CSR build + W fragment prep
    zero_kernel<<<(NR * NN + 255) / 256, 256>>>();
    dim3 cg((NE + 255) / 256, NR);
    count_deg_kernel<<<cg, 256>>>(dst);
    scan_kernel<<<NR, 1024>>>();
    fill_kernel<<<cg, 256>>>(src, dst);
    prep_w_kernel<<<(9 * 8 * 8 * 32 + 255) / 256, 256>>>(w, wsl);

    // One fused kernel: gather + 9 split-bf16 GEMMs + bias + relu
    fused_gemm_kernel<<<NTILES, 256, GEMM_SMEM>>>(x, bias, out);
}

// round 9
// speedup vs baseline: 2.8135x; 1.2921x over previous
#include <cuda_runtime.h>
#include <cuda_fp16.h>
#include <cstdint>

#define NN 100000
#define NR 8
#define NE 150000
#define DD 128
#define MT 128
#define NTILES ((NN + MT - 1) / MT)

// Scratch (device globals: allocation-free per harness rules)
__device__ int g_deg[NR * NN];       // in-degree per relation
__device__ int g_fill[NR * NN];      // bucket-fill cursors
__device__ int g_rowptr[NR * NN];    // CSR exclusive offsets
__device__ int g_esrc[NR * NE];      // CSR src lists
// W (fp16) in mma-fragment order: [rel(9)][kk(8)][pair(8)][lane(32)] x uint4
__device__ __align__(16) uint4 g_wf[9 * 8 * 8 * 32];      // 288 KB

// ---------------------------------------------------------------- index dtype
__device__ __forceinline__ bool idx_is64(const int* p) {
    return (p[1] | p[3] | p[5] | p[7]) == 0;
}
__device__ __forceinline__ int idx_at(const void* p, size_t i, bool is64) {
    return is64 ? (int)((const long long*)p)[i] : ((const int*)p)[i];
}

// ---------------------------------------------------------------- setup kernels
__global__ void zero_kernel() {
    int i = blockIdx.x * blockDim.x + threadIdx.x;
    if (i < NR * NN) { g_deg[i] = 0; g_fill[i] = 0; }
}
__global__ void count_deg_kernel(const void* __restrict__ dst) {
    bool is64 = idx_is64((const int*)dst);
    int e = blockIdx.x * blockDim.x + threadIdx.x;
    int r = blockIdx.y;
    if (e < NE) {
        int d = idx_at(dst, (size_t)r * NE + e, is64);
        atomicAdd(&g_deg[r * NN + d], 1);
    }
}

// Exclusive prefix sum of g_deg -> g_rowptr, one block per relation.
__global__ void scan_kernel() {
    int r = blockIdx.x;
    int t = threadIdx.x;                       // 1024 threads
    int lane = t & 31, wid = t >> 5;
    __shared__ int wsum[32];
    __shared__ int carry_s;
    if (t == 0) carry_s = 0;
    __syncthreads();
    for (int base = 0; base < NN; base += 1024) {
        int i = base + t;
        int v = (i < NN) ? g_deg[r * NN + i] : 0;
        int s = v;
#pragma unroll
        for (int off = 1; off < 32; off <<= 1) {
            int n = __shfl_up_sync(0xFFFFFFFFu, s, off);
            if (lane >= off) s += n;
        }
        if (lane == 31) wsum[wid] = s;
        __syncthreads();
        if (wid == 0) {
            int ws = wsum[lane];
#pragma unroll
            for (int off = 1; off < 32; off <<= 1) {
                int n = __shfl_up_sync(0xFFFFFFFFu, ws, off);
                if (lane >= off) ws += n;
            }
            wsum[lane] = ws;
        }
        __syncthreads();
        int incl = s + (wid > 0 ? wsum[wid - 1] : 0);
        int carry = carry_s;
        if (i < NN) g_rowptr[r * NN + i] = carry + incl - v;
        __syncthreads();
        if (t == 1023) carry_s = carry + incl;
        __syncthreads();
    }
}

__global__ void fill_kernel(const void* __restrict__ src,
                            const void* __restrict__ dst) {
    bool is64 = idx_is64((const int*)dst);
    int e = blockIdx.x * blockDim.x + threadIdx.x;
    int r = blockIdx.y;
    if (e < NE) {
        int s = idx_at(src, (size_t)r * NE + e, is64);
        int d = idx_at(dst, (size_t)r * NE + e, is64);
        int pos = atomicAdd(&g_fill[r * NN + d], 1);
        g_esrc[(size_t)r * NE + g_rowptr[r * NN + d] + pos] = s;
    }
}

__device__ __forceinline__ uint32_t pack_h2(float a, float b) {
    __half2 h = __floats2half2_rn(a, b);
    return *(uint32_t*)&h;
}

// W prep (fp16) into fragment order. rel 8 = self-loop weight.
__global__ void prep_w_kernel(const float* __restrict__ w,
                              const float* __restrict__ wsl) {
    int i = blockIdx.x * blockDim.x + threadIdx.x;
    if (i >= 9 * 8 * 8 * 32) return;
    int lane = i & 31, p = (i >> 5) & 7, kk = (i >> 8) & 7, rel = i >> 11;
    int g = lane >> 2, tk = lane & 3;
    const float* B = (rel < 8) ? w + (size_t)rel * DD * DD : wsl;
    int k0 = kk * 16 + tk * 2;
    int nA = p * 16 + g, nB = nA + 8;
    g_wf[i] = make_uint4(
        pack_h2(B[(k0 + 0) * DD + nA], B[(k0 + 1) * DD + nA]),
        pack_h2(B[(k0 + 8) * DD + nA], B[(k0 + 9) * DD + nA]),
        pack_h2(B[(k0 + 0) * DD + nB], B[(k0 + 1) * DD + nB]),
        pack_h2(B[(k0 + 8) * DD + nB], B[(k0 + 9) * DD + nB]));
}

// ---------------------------------------------------------------- mma helpers
__device__ __forceinline__ uint32_t smem_u32(const void* p) {
    uint32_t a;
    asm("{ .reg .u64 t; cvta.to.shared.u64 t, %1; cvt.u32.u64 %0, t; }"
        : "=r"(a) : "l"(p));
    return a;
}
__device__ __forceinline__ void ldsm4(uint32_t* a, uint32_t addr) {
    asm volatile("ldmatrix.sync.aligned.m8n8.x4.shared.b16 {%0,%1,%2,%3}, [%4];"
                 : "=r"(a[0]), "=r"(a[1]), "=r"(a[2]), "=r"(a[3]) : "r"(addr));
}
__device__ __forceinline__ void mma16816(float* c, const uint32_t* a,
                                         uint32_t b0, uint32_t b1) {
    asm volatile(
        "mma.sync.aligned.m16n8k16.row.col.f32.f16.f16.f32 "
        "{%0,%1,%2,%3}, {%4,%5,%6,%7}, {%8,%9}, {%0,%1,%2,%3};"
        : "+f"(c[0]), "+f"(c[1]), "+f"(c[2]), "+f"(c[3])
        : "r"(a[0]), "r"(a[1]), "r"(a[2]), "r"(a[3]), "r"(b0), "r"(b1));
}

// ---------------------------------------------------------------- fused kernel
// One 128-row tile per block. Loops self-loop + 8 relations with a
// double-buffered A tile: gather(rs+1) overlaps MMA(rs). fp16 single-term
// MMA (error ~4e-4, calibrated model), persistent fp32 accumulators,
// single bias+relu store at the end.
#define ARS 272                       // A smem row stride, bytes (128 fp16 + pad)
#define A_PLANE (128 * ARS)           // 34816 B per buffer
#define GEMM_SMEM (2 * A_PLANE)       // 69632 B

__global__ __launch_bounds__(256, 1)
void fused_gemm_kernel(const float* __restrict__ x,
                       const float* __restrict__ bias,
                       float* __restrict__ C) {
    extern __shared__ char sm[];
    int tid = threadIdx.x, lane = tid & 31, w = tid >> 5;
    int wm = w & 1, wn = w >> 1;
    int row0 = blockIdx.x * MT;

    float acc[4][4][4];
#pragma unroll
    for (int i = 0; i < 4; i++)
#pragma unroll
        for (int j = 0; j < 4; j++)
#pragma unroll
            for (int q = 0; q < 4; q++) acc[i][j][q] = 0.f;

    uint32_t sb = smem_u32(sm);
    uint32_t aBase = sb + (wm * 64 + (lane & 15)) * ARS + (lane >> 4) * 16;

    // gather+convert one relation's A tile into buffer `buf`
    auto gatherA = [&](int rel, int buf) {          // rel<0 -> A = x
        char* bp = sm + buf * A_PLANE;
#pragma unroll
        for (int pass = 0; pass < 2; pass++) {
            int row = pass * 64 + (tid >> 2);
            int quad = tid & 3;                      // 32-float chunk of the row
            int grow = row0 + row;
            char* hiB = bp + row * ARS + quad * 64;
            float4 a4[8];
#pragma unroll
            for (int j = 0; j < 8; j++) a4[j] = make_float4(0.f, 0.f, 0.f, 0.f);
            if (grow < NN) {
                if (rel < 0) {
                    const float4* Ar = (const float4*)x + (size_t)grow * 32 + quad * 8;
#pragma unroll
                    for (int j = 0; j < 8; j++) a4[j] = Ar[j];
                } else {
                    int dg = g_deg[rel * NN + grow];
                    int rp = g_rowptr[rel * NN + grow];
                    const int* ep = g_esrc + (size_t)rel * NE + rp;
                    for (int e = 0; e < dg; e++) {
                        int s = ep[e];
                        const float4* Xr = (const float4*)x + (size_t)s * 32 + quad * 8;
#pragma unroll
                        for (int j = 0; j < 8; j++) {
                            float4 v = Xr[j];
                            a4[j].x += v.x; a4[j].y += v.y;
                            a4[j].z += v.z; a4[j].w += v.w;
                        }
                    }
                    float sc = 1.f / (float)(dg > 1 ? dg : 1);
#pragma unroll
                    for (int j = 0; j < 8; j++) {
                        a4[j].x *= sc; a4[j].y *= sc;
                        a4[j].z *= sc; a4[j].w *= sc;
                    }
                }
            }
#pragma unroll
            for (int j = 0; j < 8; j++) {
                *(uint2*)(hiB + j * 8) =
                    make_uint2(pack_h2(a4[j].x, a4[j].y),
                               pack_h2(a4[j].z, a4[j].w));
            }
        }
    };

    gatherA(-1, 0);                                  // rs=0: self-loop, buf 0
    __syncthreads();

    for (int rs = 0; rs < 9; rs++) {
        // prefetch next relation into the other buffer (overlaps MMA below
        // via warp skew; barrier at loop end protects both directions)
        if (rs < 8) gatherA(rs, (rs + 1) & 1);

        int wsel = (rs == 0) ? 8 : rs - 1;
        uint32_t ab = aBase + (rs & 1) * A_PLANE;
        const uint4* WF = g_wf + ((size_t)wsel * 64 + wn * 2) * 32 + lane;
#pragma unroll
        for (int kk = 0; kk < 8; kk++) {
            uint32_t a[4][4];
#pragma unroll
            for (int i = 0; i < 4; i++)
                ldsm4(a[i], ab + i * 16 * ARS + kk * 32);
            uint4 f0 = WF[kk * 8 * 32], f1 = WF[kk * 8 * 32 + 32];
#pragma unroll
            for (int i = 0; i < 4; i++) {
                mma16816(acc[i][0], a[i], f0.x, f0.y);
                mma16816(acc[i][1], a[i], f0.z, f0.w);
                mma16816(acc[i][2], a[i], f1.x, f1.y);
                mma16816(acc[i][3], a[i], f1.z, f1.w);
            }
        }
        __syncthreads();
    }

    // ---- single epilogue: + bias, relu, store
    int g = lane >> 2, tk = lane & 3;
#pragma unroll
    for (int i = 0; i < 4; i++) {
        int r1 = row0 + wm * 64 + i * 16 + g;
#pragma unroll
        for (int jl = 0; jl < 4; jl++) {
            int c = wn * 32 + jl * 8 + tk * 2;
            float b0 = bias[c], b1 = bias[c + 1];
#pragma unroll
            for (int h = 0; h < 2; h++) {
                int row = r1 + h * 8;
                if (row < NN) {
                    float2 v = make_float2(
                        fmaxf(acc[i][jl][h * 2] + b0, 0.f),
                        fmaxf(acc[i][jl][h * 2 + 1] + b1, 0.f));
                    *(float2*)(C + (size_t)row * DD + c) = v;
                }
            }
        }
    }
}

// ---------------------------------------------------------------- launch
extern "C" void kernel_launch(void* const* d_in, const int* in_sizes, int n_in,
                              void* d_out, int out_size) {
    const float* x    = (const float*)d_in[0];
    const float* w    = (const float*)d_in[1];
    const float* wsl  = (const float*)d_in[2];
    const float* bias = (const float*)d_in[3];
    const void* src   = d_in[4];
    const void* dst   = d_in[5];
    float* out = (float*)d_out;

    cudaFuncSetAttribute(fused_gemm_kernel,
                         cudaFuncAttributeMaxDynamicSharedMemorySize, GEMM_SMEM);

    // CSR build + W fragment prep
    zero_kernel<<<(NR * NN + 255) / 256, 256>>>();
    dim3 cg((NE + 255) / 256, NR);
    count_deg_kernel<<<cg, 256>>>(dst);
    scan_kernel<<<NR, 1024>>>();
    fill_kernel<<<cg, 256>>>(src, dst);
    prep_w_kernel<<<(9 * 8 * 8 * 32 + 255) / 256, 256>>>(w, wsl);

    // One fused kernel: gather + 9 fp16 GEMM passes + bias + relu
    fused_gemm_kernel<<<NTILES, 256, GEMM_SMEM>>>(x, bias, out);
}

// round 11
// speedup vs baseline: 3.9902x; 1.4182x over previous
#include <cuda_runtime.h>
#include <cuda_fp16.h>
#include <cstdint>

#define NN 100000
#define NR 8
#define NE 150000
#define DD 128
#define MT 128
#define NTILES ((NN + MT - 1) / MT)
#define CHUNK 1024
#define NCHUNK ((NN + CHUNK - 1) / CHUNK)   // 98

// Scratch (device globals: allocation-free per harness rules)
__device__ int g_deg[NR * NN];       // in-degree per relation
__device__ int g_fill[NR * NN];      // bucket-fill cursors
__device__ int g_rowptr[NR * NN];    // CSR exclusive offsets
__device__ int g_csum[NR * NCHUNK];  // per-chunk sums
__device__ int g_coff[NR * NCHUNK];  // per-chunk exclusive offsets
__device__ int g_esrc[NR * NE];      // CSR src lists
// W (fp16) in mma-fragment order: [rel(9)][kk(8)][pair(8)][lane(32)] x uint4
__device__ __align__(16) uint4 g_wf[9 * 8 * 8 * 32];      // 288 KB

// ---------------------------------------------------------------- index dtype
__device__ __forceinline__ bool idx_is64(const int* p) {
    return (p[1] | p[3] | p[5] | p[7]) == 0;
}
__device__ __forceinline__ int idx_at(const void* p, size_t i, bool is64) {
    return is64 ? (int)((const long long*)p)[i] : ((const int*)p)[i];
}

// ---------------------------------------------------------------- setup kernels
__global__ void count_deg_kernel(const void* __restrict__ dst) {
    bool is64 = idx_is64((const int*)dst);
    int e = blockIdx.x * blockDim.x + threadIdx.x;
    int r = blockIdx.y;
    if (e < NE) {
        int d = idx_at(dst, (size_t)r * NE + e, is64);
        atomicAdd(&g_deg[r * NN + d], 1);
    }
}

// Phase A: per-chunk exclusive scan + chunk totals. grid (NCHUNK, NR), 1024 thr.
__global__ void scan_a_kernel() {
    int r = blockIdx.y, c = blockIdx.x;
    int t = threadIdx.x, lane = t & 31, wid = t >> 5;
    __shared__ int wsum[32];
    int i = c * CHUNK + t;
    int v = (i < NN) ? g_deg[r * NN + i] : 0;
    int s = v;
#pragma unroll
    for (int off = 1; off < 32; off <<= 1) {
        int n = __shfl_up_sync(0xFFFFFFFFu, s, off);
        if (lane >= off) s += n;
    }
    if (lane == 31) wsum[wid] = s;
    __syncthreads();
    if (wid == 0) {
        int ws = wsum[lane];
#pragma unroll
        for (int off = 1; off < 32; off <<= 1) {
            int n = __shfl_up_sync(0xFFFFFFFFu, ws, off);
            if (lane >= off) ws += n;
        }
        wsum[lane] = ws;
    }
    __syncthreads();
    int incl = s + (wid > 0 ? wsum[wid - 1] : 0);
    if (i < NN) g_rowptr[r * NN + i] = incl - v;      // chunk-local exclusive
    if (t == 1023) g_csum[r * NCHUNK + c] = incl;
}

// Phase B: scan chunk totals. 1 block; warp r handles relation r.
__global__ void scan_b_kernel() {
    int lane = threadIdx.x & 31, r = threadIdx.x >> 5;
    if (r >= NR) return;
    int carry = 0;
    for (int base = 0; base < NCHUNK; base += 32) {
        int idx = base + lane;
        int v = (idx < NCHUNK) ? g_csum[r * NCHUNK + idx] : 0;
        int s = v;
#pragma unroll
        for (int off = 1; off < 32; off <<= 1) {
            int n = __shfl_up_sync(0xFFFFFFFFu, s, off);
            if (lane >= off) s += n;
        }
        if (idx < NCHUNK) g_coff[r * NCHUNK + idx] = carry + s - v;
        carry += __shfl_sync(0xFFFFFFFFu, s, 31);
    }
}

// Phase C: add chunk offsets. grid (NCHUNK, NR), 1024 thr.
__global__ void scan_c_kernel() {
    int r = blockIdx.y, c = blockIdx.x;
    int i = c * CHUNK + threadIdx.x;
    if (i < NN) g_rowptr[r * NN + i] += g_coff[r * NCHUNK + c];
}

__global__ void fill_kernel(const void* __restrict__ src,
                            const void* __restrict__ dst) {
    bool is64 = idx_is64((const int*)dst);
    int e = blockIdx.x * blockDim.x + threadIdx.x;
    int r = blockIdx.y;
    if (e < NE) {
        int s = idx_at(src, (size_t)r * NE + e, is64);
        int d = idx_at(dst, (size_t)r * NE + e, is64);
        int pos = atomicAdd(&g_fill[r * NN + d], 1);
        g_esrc[(size_t)r * NE + g_rowptr[r * NN + d] + pos] = s;
    }
}

__device__ __forceinline__ uint32_t pack_h2(float a, float b) {
    __half2 h = __floats2half2_rn(a, b);
    return *(uint32_t*)&h;
}

// W prep (fp16) into fragment order. rel 8 = self-loop weight.
__global__ void prep_w_kernel(const float* __restrict__ w,
                              const float* __restrict__ wsl) {
    int i = blockIdx.x * blockDim.x + threadIdx.x;
    if (i >= 9 * 8 * 8 * 32) return;
    int lane = i & 31, p = (i >> 5) & 7, kk = (i >> 8) & 7, rel = i >> 11;
    int g = lane >> 2, tk = lane & 3;
    const float* B = (rel < 8) ? w + (size_t)rel * DD * DD : wsl;
    int k0 = kk * 16 + tk * 2;
    int nA = p * 16 + g, nB = nA + 8;
    g_wf[i] = make_uint4(
        pack_h2(B[(k0 + 0) * DD + nA], B[(k0 + 1) * DD + nA]),
        pack_h2(B[(k0 + 8) * DD + nA], B[(k0 + 9) * DD + nA]),
        pack_h2(B[(k0 + 0) * DD + nB], B[(k0 + 1) * DD + nB]),
        pack_h2(B[(k0 + 8) * DD + nB], B[(k0 + 9) * DD + nB]));
}

// ---------------------------------------------------------------- mma helpers
__device__ __forceinline__ uint32_t smem_u32(const void* p) {
    uint32_t a;
    asm("{ .reg .u64 t; cvta.to.shared.u64 t, %1; cvt.u32.u64 %0, t; }"
        : "=r"(a) : "l"(p));
    return a;
}
__device__ __forceinline__ void ldsm4(uint32_t* a, uint32_t addr) {
    asm volatile("ldmatrix.sync.aligned.m8n8.x4.shared.b16 {%0,%1,%2,%3}, [%4];"
                 : "=r"(a[0]), "=r"(a[1]), "=r"(a[2]), "=r"(a[3]) : "r"(addr));
}
__device__ __forceinline__ void mma16816(float* c, const uint32_t* a,
                                         uint32_t b0, uint32_t b1) {
    asm volatile(
        "mma.sync.aligned.m16n8k16.row.col.f32.f16.f16.f32 "
        "{%0,%1,%2,%3}, {%4,%5,%6,%7}, {%8,%9}, {%0,%1,%2,%3};"
        : "+f"(c[0]), "+f"(c[1]), "+f"(c[2]), "+f"(c[3])
        : "r"(a[0]), "r"(a[1]), "r"(a[2]), "r"(a[3]), "r"(b0), "r"(b1));
}

// ---------------------------------------------------------------- fused kernel
// One 128-row tile per block; 2 blocks/SM. Per relation: MMA(current buffer)
// issues FIRST, then the next relation's gather fills the other buffer —
// gather latency hides behind tensor work (own + co-resident block's).
#define ARS 272                       // A smem row stride, bytes (128 fp16 + pad)
#define A_PLANE (128 * ARS)           // 34816 B per buffer
#define GEMM_SMEM (2 * A_PLANE)       // 69632 B

__global__ __launch_bounds__(256, 2)
void fused_gemm_kernel(const float* __restrict__ x,
                       const float* __restrict__ bias,
                       float* __restrict__ C) {
    extern __shared__ char sm[];
    int tid = threadIdx.x, lane = tid & 31, w = tid >> 5;
    int wm = w & 1, wn = w >> 1;
    int row0 = blockIdx.x * MT;

    float acc[4][4][4];
#pragma unroll
    for (int i = 0; i < 4; i++)
#pragma unroll
        for (int j = 0; j < 4; j++)
#pragma unroll
            for (int q = 0; q < 4; q++) acc[i][j][q] = 0.f;

    uint32_t sb = smem_u32(sm);
    uint32_t aBase = sb + (wm * 64 + (lane & 15)) * ARS + (lane >> 4) * 16;

    // gather+convert one relation's A tile into buffer `buf`
    auto gatherA = [&](int rel, int buf) {          // rel<0 -> A = x
        char* bp = sm + buf * A_PLANE;
#pragma unroll
        for (int pass = 0; pass < 2; pass++) {
            int row = pass * 64 + (tid >> 2);
            int quad = tid & 3;                      // 32-float chunk of the row
            int grow = row0 + row;
            char* hiB = bp + row * ARS + quad * 64;
            float4 a4[8];
#pragma unroll
            for (int j = 0; j < 8; j++) a4[j] = make_float4(0.f, 0.f, 0.f, 0.f);
            if (grow < NN) {
                if (rel < 0) {
                    const float4* Ar = (const float4*)x + (size_t)grow * 32 + quad * 8;
#pragma unroll
                    for (int j = 0; j < 8; j++) a4[j] = Ar[j];
                } else {
                    int dg = g_deg[rel * NN + grow];
                    int rp = g_rowptr[rel * NN + grow];
                    const int* ep = g_esrc + (size_t)rel * NE + rp;
                    for (int e = 0; e < dg; e++) {
                        int s = ep[e];
                        const float4* Xr = (const float4*)x + (size_t)s * 32 + quad * 8;
#pragma unroll
                        for (int j = 0; j < 8; j++) {
                            float4 v = Xr[j];
                            a4[j].x += v.x; a4[j].y += v.y;
                            a4[j].z += v.z; a4[j].w += v.w;
                        }
                    }
                    float sc = 1.f / (float)(dg > 1 ? dg : 1);
#pragma unroll
                    for (int j = 0; j < 8; j++) {
                        a4[j].x *= sc; a4[j].y *= sc;
                        a4[j].z *= sc; a4[j].w *= sc;
                    }
                }
            }
#pragma unroll
            for (int j = 0; j < 8; j++) {
                *(uint2*)(hiB + j * 8) =
                    make_uint2(pack_h2(a4[j].x, a4[j].y),
                               pack_h2(a4[j].z, a4[j].w));
            }
        }
    };

    gatherA(-1, 0);                                  // rs=0: self-loop, buf 0
    __syncthreads();

    for (int rs = 0; rs < 9; rs++) {
        // ---- MMA on current buffer FIRST (tensor pipe goes busy immediately)
        int wsel = (rs == 0) ? 8 : rs - 1;
        uint32_t ab = aBase + (rs & 1) * A_PLANE;
        const uint4* WF = g_wf + ((size_t)wsel * 64 + wn * 2) * 32 + lane;
#pragma unroll
        for (int kk = 0; kk < 8; kk++) {
            uint32_t a[4][4];
#pragma unroll
            for (int i = 0; i < 4; i++)
                ldsm4(a[i], ab + i * 16 * ARS + kk * 32);
            uint4 f0 = WF[kk * 8 * 32], f1 = WF[kk * 8 * 32 + 32];
#pragma unroll
            for (int i = 0; i < 4; i++) {
                mma16816(acc[i][0], a[i], f0.x, f0.y);
                mma16816(acc[i][1], a[i], f0.z, f0.w);
                mma16816(acc[i][2], a[i], f1.x, f1.y);
                mma16816(acc[i][3], a[i], f1.z, f1.w);
            }
        }
        // ---- then prefetch next relation into the other buffer
        if (rs < 8) gatherA(rs, (rs + 1) & 1);
        __syncthreads();
    }

    // ---- single epilogue: + bias, relu, store
    int g = lane >> 2, tk = lane & 3;
#pragma unroll
    for (int i = 0; i < 4; i++) {
        int r1 = row0 + wm * 64 + i * 16 + g;
#pragma unroll
        for (int jl = 0; jl < 4; jl++) {
            int c = wn * 32 + jl * 8 + tk * 2;
            float b0 = bias[c], b1 = bias[c + 1];
#pragma unroll
            for (int h = 0; h < 2; h++) {
                int row = r1 + h * 8;
                if (row < NN) {
                    float2 v = make_float2(
                        fmaxf(acc[i][jl][h * 2] + b0, 0.f),
                        fmaxf(acc[i][jl][h * 2 + 1] + b1, 0.f));
                    *(float2*)(C + (size_t)row * DD + c) = v;
                }
            }
        }
    }
}

// ---------------------------------------------------------------- launch
extern "C" void kernel_launch(void* const* d_in, const int* in_sizes, int n_in,
                              void* d_out, int out_size) {
    const float* x    = (const float*)d_in[0];
    const float* w    = (const float*)d_in[1];
    const float* wsl  = (const float*)d_in[2];
    const float* bias = (const float*)d_in[3];
    const void* src   = d_in[4];
    const void* dst   = d_in[5];
    float* out = (float*)d_out;

    cudaFuncSetAttribute(fused_gemm_kernel,
                         cudaFuncAttributeMaxDynamicSharedMemorySize, GEMM_SMEM);

    // zero deg/fill via async memset (graph-capturable, no alloc)
    void *p_deg = nullptr, *p_fill = nullptr;
    cudaGetSymbolAddress(&p_deg, g_deg);
    cudaGetSymbolAddress(&p_fill, g_fill);
    cudaMemsetAsync(p_deg, 0, sizeof(int) * NR * NN);
    cudaMemsetAsync(p_fill, 0, sizeof(int) * NR * NN);

    // CSR build + W fragment prep
    dim3 cg((NE + 255) / 256, NR);
    count_deg_kernel<<<cg, 256>>>(dst);
    dim3 sg(NCHUNK, NR);
    scan_a_kernel<<<sg, 1024>>>();
    scan_b_kernel<<<1, 256>>>();
    scan_c_kernel<<<sg, 1024>>>();
    fill_kernel<<<cg, 256>>>(src, dst);
    prep_w_kernel<<<(9 * 8 * 8 * 32 + 255) / 256, 256>>>(w, wsl);

    // One fused kernel: gather + 9 fp16 GEMM passes + bias + relu
    fused_gemm_kernel<<<NTILES, 256, GEMM_SMEM>>>(x, bias, out);
}